// round 11
// baseline (speedup 1.0000x reference)
#include <cuda_runtime.h>
#include <cuda_bf16.h>

#define NN 8192
#define DCAP 64u              // adjacency slots per node (P(deg>64) ~ 1e-15)
#define OVF_CAP (1u << 16)    // spill safety

// Static scratch. d_deg/counters re-zeroed by hc_finish each run.
__device__ unsigned int d_deg[NN];              // zero at load
__device__ unsigned short d_adj[NN * DCAP];     // 1MB adjacency (u16 ids)
__device__ unsigned int d_ucount;               // strictly-upper positives
__device__ unsigned int d_dcount;               // diagonal positives
__device__ unsigned int d_ovfcnt;
__device__ unsigned int d_ovf[OVF_CAP];

// Scatter one undirected edge into both endpoints' adjacency rows.
// Runs in the scan's rare path: L2 atomics distributed across 4096 blocks,
// hidden under the memory-bound stream.
__device__ __forceinline__ void scatter_edge(int u, int v) {
    unsigned su = atomicAdd(&d_deg[u], 1u);
    unsigned sv = atomicAdd(&d_deg[v], 1u);
    bool ou = su >= DCAP, ov = sv >= DCAP;
    if (!ou) d_adj[((unsigned)u << 6) + su] = (unsigned short)v;
    if (!ov) d_adj[((unsigned)v << 6) + sv] = (unsigned short)u;
    if (ou | ov) {
        unsigned o = atomicAdd(&d_ovfcnt, 1u);
        if (o < OVF_CAP) d_ovf[o] = ((unsigned)u << 13) | (unsigned)v;
    }
}

// Upper-triangle scan, block per row pair (row, NN-1-row): NN+1 elements per
// block -> perfect balance. Hot loop (proven ~4.3 TB/s): 4 batched LDG.128,
// straight-line count, one uniform warp branch via ballot; hits scatter into
// the adjacency and bump a SMEM counter.
// Exactness: adj bitwise symmetric -> full positives = 2U + D; the
// reference's sum(adj>0)//2 = U + D//2 exactly.
__global__ void __launch_bounds__(256) hc_scan(const float* __restrict__ adj) {
    __shared__ unsigned s_cnt;
    const int t = threadIdx.x;
    const int pair = blockIdx.x;
    if (t == 0) s_cnt = 0u;
    __syncthreads();

    #pragma unroll
    for (int half = 0; half < 2; half++) {
        const int row = half ? (NN - 1 - pair) : pair;
        const float4* __restrict__ rowp = (const float4*)(adj + (size_t)row * NN);
        const int start4 = row >> 2;            // quad containing the diagonal

        if (t == 0) {
            // diagonal quad: cols may be <, ==, or > row
            float4 v = rowp[start4];
            int col0 = start4 << 2;
            float e[4] = {v.x, v.y, v.z, v.w};
            unsigned dd = 0, uu = 0;
            #pragma unroll
            for (int j = 0; j < 4; j++) {
                int col = col0 + j;
                if (e[j] > 0.0f) {
                    if (col == row) dd++;
                    else if (col > row) { uu++; scatter_edge(row, col); }
                }
            }
            if (dd) atomicAdd(&d_dcount, dd);
            if (uu) atomicAdd(&s_cnt, uu);
        }

        const int lim = NN / 4;
        for (int ib = start4 + 1; ib < lim; ib += 1024) {
            const float4 NEG = make_float4(-1.f, -1.f, -1.f, -1.f);
            const int i0 = ib + t;
            float4 v0 = NEG, v1 = NEG, v2 = NEG, v3 = NEG;
            if (i0       < lim) v0 = rowp[i0];
            if (i0 + 256 < lim) v1 = rowp[i0 + 256];
            if (i0 + 512 < lim) v2 = rowp[i0 + 512];
            if (i0 + 768 < lim) v3 = rowp[i0 + 768];

            unsigned k = (unsigned)(v0.x > 0.f) + (unsigned)(v0.y > 0.f)
                       + (unsigned)(v0.z > 0.f) + (unsigned)(v0.w > 0.f)
                       + (unsigned)(v1.x > 0.f) + (unsigned)(v1.y > 0.f)
                       + (unsigned)(v1.z > 0.f) + (unsigned)(v1.w > 0.f)
                       + (unsigned)(v2.x > 0.f) + (unsigned)(v2.y > 0.f)
                       + (unsigned)(v2.z > 0.f) + (unsigned)(v2.w > 0.f)
                       + (unsigned)(v3.x > 0.f) + (unsigned)(v3.y > 0.f)
                       + (unsigned)(v3.z > 0.f) + (unsigned)(v3.w > 0.f);

            if (__ballot_sync(0xFFFFFFFFu, k != 0u)) {
                if (k) {
                    atomicAdd(&s_cnt, k);
                    #pragma unroll
                    for (int q = 0; q < 4; q++) {
                        float4 v = (q == 0) ? v0 : (q == 1) ? v1 : (q == 2) ? v2 : v3;
                        int col0 = (i0 + q * 256) << 2;
                        float e[4] = {v.x, v.y, v.z, v.w};
                        #pragma unroll
                        for (int j = 0; j < 4; j++)
                            if (e[j] > 0.f) scatter_edge(row, col0 + j);
                    }
                }
            }
        }
    }

    __syncthreads();
    if (t == 0 && s_cnt) atomicAdd(&d_ucount, s_cnt);
}

// Single block, 1024 threads: pull-based min-label CC with OWNER-ONLY label
// writes (zero atomics on the fast path — smem ATOMS throughput was the
// 50us bottleneck). Each thread owns 8 nodes; per pass it gathers neighbor
// labels in branch-free uint4 chunks (rows padded with self-ids) and lowers
// its own labels with plain stores. Monotone + owner-only => races benign.
// A pass with no change and no mismatched overflow edge => labels constant
// per component => lab[i]==i exactly at each component's min node.
__global__ void __launch_bounds__(1024) hc_finish(float* __restrict__ out) {
    __shared__ int lab[NN];                  // 32KB
    __shared__ int sh[1024];
    __shared__ int s_changed;
    const int t = threadIdx.x;

    int deg[8], ch[8];
    #pragma unroll
    for (int k = 0; k < 8; k++) {
        int i = t + k * 1024;
        lab[i] = i;
        int d = (int)min(d_deg[i], DCAP);
        deg[k] = d;
        ch[k] = (d + 7) >> 3;
        // pad row to a uint4 boundary with self-ids (row read only by owner)
        int pad_end = ch[k] << 3;
        for (int p = d; p < pad_end; p++)
            d_adj[((unsigned)i << 6) + p] = (unsigned short)i;
    }
    __syncthreads();

    const unsigned novf = min(d_ovfcnt, OVF_CAP);
    const bool use_atomic = (novf != 0);     // all-atomic fallback (never taken here)

    for (int iter = 0; iter < 64; iter++) {
        if (t == 0) s_changed = 0;
        __syncthreads();

        // pull pass: 8 nodes per thread, 8 neighbors per chunk
        #pragma unroll
        for (int k = 0; k < 8; k++) {
            int i = t + k * 1024;
            int m = lab[i];
            const uint4* ap = (const uint4*)(d_adj + ((unsigned)i << 6));
            for (int c = 0; c < ch[k]; c++) {
                uint4 q = ap[c];
                int a0 = (int)(q.x & 0xFFFFu), a1 = (int)(q.x >> 16);
                int a2 = (int)(q.y & 0xFFFFu), a3 = (int)(q.y >> 16);
                int a4 = (int)(q.z & 0xFFFFu), a5 = (int)(q.z >> 16);
                int a6 = (int)(q.w & 0xFFFFu), a7 = (int)(q.w >> 16);
                int m0 = min(lab[a0], lab[a1]);
                int m1 = min(lab[a2], lab[a3]);
                int m2 = min(lab[a4], lab[a5]);
                int m3 = min(lab[a6], lab[a7]);
                m = min(m, min(min(m0, m1), min(m2, m3)));
            }
            if (m < lab[i]) {
                if (use_atomic) atomicMin(&lab[i], m); else lab[i] = m;
                s_changed = 1;
            }
        }
        // overflow edges (expected zero)
        for (unsigned idx = t; idx < novf; idx += 1024) {
            unsigned e = d_ovf[idx];
            int u = (int)(e >> 13), v = (int)(e & 8191u);
            int lu = lab[u], lv = lab[v];
            if (lu != lv) {
                s_changed = 1;
                if (lu < lv) atomicMin(&lab[v], lu);
                else         atomicMin(&lab[u], lv);
            }
        }
        __syncthreads();
        if (!s_changed) break;

        // pointer-jump x2 (owner-only; lab[x] <= x invariant keeps it monotone)
        #pragma unroll
        for (int r = 0; r < 2; r++) {
            #pragma unroll
            for (int k = 0; k < 8; k++) {
                int i = t + k * 1024;
                int j = lab[i];
                int lj = lab[j];
                if (lj < j) {
                    if (use_atomic) atomicMin(&lab[i], lj); else lab[i] = lj;
                }
            }
            __syncthreads();
        }
    }
    __syncthreads();

    int roots = 0;
    #pragma unroll
    for (int k = 0; k < 8; k++) {
        int i = t + k * 1024;
        roots += (lab[i] == i) ? 1 : 0;
    }
    sh[t] = roots;
    __syncthreads();
    for (int s = 512; s > 0; s >>= 1) {
        if (t < s) sh[t] += sh[t + s];
        __syncthreads();
    }
    if (t == 0) {
        float n_comp  = (float)sh[0];
        unsigned half_edges = d_ucount + (d_dcount >> 1);   // (2U+D)//2
        float n_edges = (float)half_edges;
        float betti1  = n_edges - (float)NN + n_comp;
        float n_cyc   = fmaxf(0.0f, betti1);
        float comp_l  = (n_comp - 1.0f) * (n_comp - 1.0f);
        out[0] = comp_l + n_cyc * n_cyc;
    }
    // reset state for the next replay
    #pragma unroll
    for (int k = 0; k < 8; k++)
        d_deg[t + k * 1024] = 0u;
    if (t == 0) { d_ucount = 0u; d_dcount = 0u; d_ovfcnt = 0u; }
}

extern "C" void kernel_launch(void* const* d_in, const int* in_sizes, int n_in,
                              void* d_out, int out_size) {
    const float* adj = (const float*)d_in[0];
    float* out = (float*)d_out;

    hc_scan<<<NN / 2, 256>>>(adj);
    hc_finish<<<1, 1024>>>(out);
}

// round 12
// speedup vs baseline: 1.2884x; 1.2884x over previous
#include <cuda_runtime.h>
#include <cuda_bf16.h>

#define NN 8192
#define NOWN 1024u            // owner threads; node n owned by (n & 1023)
#define CAPB 256u             // bucket entries per owner (avg ~152, 5 sigma < 256)
#define NCHUNK (CAPB / 8u)    // 32 chunks of 8 u16 entries
#define OVF_CAP (1u << 16)    // spill safety

// Static scratch. All counters reset by hc_finish each run.
__device__ unsigned int d_bcnt[NOWN];                 // zero at load
__device__ unsigned short d_b[NCHUNK * 8192u];        // 512KB owner-interleaved buckets
__device__ unsigned int d_ucount;                     // strictly-upper positives
__device__ unsigned int d_dcount;                     // diagonal positives
__device__ unsigned int d_ovfcnt;
__device__ unsigned int d_ovf[OVF_CAP];

// Scatter one directed entry into the destination node's owner bucket.
// Layout: chunk c holds 8 entries per owner at d_b[c*8192 + owner*8 + r]
// -> thread t's chunk is 16 contiguous bytes (one uint4), warp-coalesced.
// Entry u16 = (node>>10)<<13 | other  (3-bit local slot + 13-bit neighbor).
__device__ __forceinline__ void scatter_dir(int node, int other) {
    unsigned owner = (unsigned)node & 1023u;
    unsigned j = atomicAdd(&d_bcnt[owner], 1u);
    if (j < CAPB) {
        unsigned addr = (j >> 3) * 8192u + owner * 8u + (j & 7u);
        d_b[addr] = (unsigned short)((((unsigned)node >> 10) << 13) | (unsigned)other);
    } else {
        unsigned o = atomicAdd(&d_ovfcnt, 1u);
        if (o < OVF_CAP) d_ovf[o] = ((unsigned)node << 13) | (unsigned)other;
    }
}

__device__ __forceinline__ void scatter_edge(int u, int v) {
    scatter_dir(u, v);
    scatter_dir(v, u);
}

// Upper-triangle scan, block per row pair (row, NN-1-row): NN+1 elements per
// block -> perfect balance. Hot loop (proven ~4.3 TB/s): 4 batched LDG.128,
// straight-line count, one uniform warp branch via ballot; hits scatter into
// owner buckets (distributed L2 atomics, hidden under the stream).
// Exactness: adj bitwise symmetric -> full positives = 2U + D; the
// reference's sum(adj>0)//2 = U + D//2 exactly.
__global__ void __launch_bounds__(256) hc_scan(const float* __restrict__ adj) {
    __shared__ unsigned s_cnt;
    const int t = threadIdx.x;
    const int pair = blockIdx.x;
    if (t == 0) s_cnt = 0u;
    __syncthreads();

    #pragma unroll
    for (int half = 0; half < 2; half++) {
        const int row = half ? (NN - 1 - pair) : pair;
        const float4* __restrict__ rowp = (const float4*)(adj + (size_t)row * NN);
        const int start4 = row >> 2;            // quad containing the diagonal

        if (t == 0) {
            // diagonal quad: cols may be <, ==, or > row
            float4 v = rowp[start4];
            int col0 = start4 << 2;
            float e[4] = {v.x, v.y, v.z, v.w};
            unsigned dd = 0, uu = 0;
            #pragma unroll
            for (int j = 0; j < 4; j++) {
                int col = col0 + j;
                if (e[j] > 0.0f) {
                    if (col == row) dd++;
                    else if (col > row) { uu++; scatter_edge(row, col); }
                }
            }
            if (dd) atomicAdd(&d_dcount, dd);
            if (uu) atomicAdd(&s_cnt, uu);
        }

        const int lim = NN / 4;
        for (int ib = start4 + 1; ib < lim; ib += 1024) {
            const float4 NEG = make_float4(-1.f, -1.f, -1.f, -1.f);
            const int i0 = ib + t;
            float4 v0 = NEG, v1 = NEG, v2 = NEG, v3 = NEG;
            if (i0       < lim) v0 = rowp[i0];
            if (i0 + 256 < lim) v1 = rowp[i0 + 256];
            if (i0 + 512 < lim) v2 = rowp[i0 + 512];
            if (i0 + 768 < lim) v3 = rowp[i0 + 768];

            unsigned k = (unsigned)(v0.x > 0.f) + (unsigned)(v0.y > 0.f)
                       + (unsigned)(v0.z > 0.f) + (unsigned)(v0.w > 0.f)
                       + (unsigned)(v1.x > 0.f) + (unsigned)(v1.y > 0.f)
                       + (unsigned)(v1.z > 0.f) + (unsigned)(v1.w > 0.f)
                       + (unsigned)(v2.x > 0.f) + (unsigned)(v2.y > 0.f)
                       + (unsigned)(v2.z > 0.f) + (unsigned)(v2.w > 0.f)
                       + (unsigned)(v3.x > 0.f) + (unsigned)(v3.y > 0.f)
                       + (unsigned)(v3.z > 0.f) + (unsigned)(v3.w > 0.f);

            if (__ballot_sync(0xFFFFFFFFu, k != 0u)) {
                if (k) {
                    atomicAdd(&s_cnt, k);
                    #pragma unroll
                    for (int q = 0; q < 4; q++) {
                        float4 v = (q == 0) ? v0 : (q == 1) ? v1 : (q == 2) ? v2 : v3;
                        int col0 = (i0 + q * 256) << 2;
                        float e[4] = {v.x, v.y, v.z, v.w};
                        #pragma unroll
                        for (int j = 0; j < 4; j++)
                            if (e[j] > 0.f) scatter_edge(row, col0 + j);
                    }
                }
            }
        }
    }

    __syncthreads();
    if (t == 0 && s_cnt) atomicAdd(&d_ucount, s_cnt);
}

// Single block, 1024 threads: owner-bucketed min-label CC. Thread t owns
// nodes {t, t+1024, ..., t+7168}; it is the ONLY writer of their labels
// (plain STS, zero atomics, monotone decreasing -> races benign, guaranteed
// convergence). Bucket reads are warp-coalesced uint4 (8 entries / lane).
// Gauss-Seidel visibility + pointer jump each iteration; __syncthreads_or
// detects the fixpoint, where labels are constant per component and
// lab[i]==i exactly at each component's min node.
__global__ void __launch_bounds__(1024) hc_finish(float* __restrict__ out) {
    __shared__ int lab[NN];                  // 32KB
    __shared__ int sh[1024];
    const int t = threadIdx.x;

    #pragma unroll
    for (int k = 0; k < 8; k++) {
        int i = t + (k << 10);
        lab[i] = i;
    }
    // pad own bucket tail to a uint4 boundary with no-op entries (local=0,
    // other = own node t -> min(lab[t], lab[t]) never fires)
    unsigned cnt = min(d_bcnt[t], CAPB);
    unsigned chunks = (cnt + 7u) >> 3;
    for (unsigned j = cnt; j < (chunks << 3); j++)
        d_b[(j >> 3) * 8192u + (unsigned)t * 8u + (j & 7u)] = (unsigned short)t;
    __syncthreads();

    const uint4* bp = (const uint4*)d_b;     // bp[c*1024 + t] = thread's chunk c
    const unsigned novf = min(d_ovfcnt, OVF_CAP);

    for (int iter = 0; iter < 64; iter++) {
        int changed = 0;

        for (unsigned c = 0; c < chunks; c++) {
            uint4 q = bp[c * 1024u + (unsigned)t];
            unsigned w[4] = {q.x, q.y, q.z, q.w};
            #pragma unroll
            for (int h = 0; h < 4; h++) {
                #pragma unroll
                for (int s = 0; s < 2; s++) {
                    unsigned e = (s == 0) ? (w[h] & 0xFFFFu) : (w[h] >> 16);
                    int other = (int)(e & 8191u);
                    int local = (int)(e >> 13);
                    int own = t + (local << 10);
                    int v = lab[other];
                    if (v < lab[own]) { lab[own] = v; changed = 1; }
                }
            }
        }
        // overflow spill (expected empty; atomics OK here)
        for (unsigned i = t; i < novf; i += 1024) {
            unsigned e = d_ovf[i];
            int u = (int)(e >> 13), v = (int)(e & 8191u);
            int lu = lab[u], lv = lab[v];
            if (lu != lv) {
                changed = 1;
                if (lu < lv) atomicMin(&lab[v], lu);
                else         atomicMin(&lab[u], lv);
            }
        }

        int any = __syncthreads_or(changed);

        // pointer jump on own nodes (owner-only, monotone)
        #pragma unroll
        for (int k = 0; k < 8; k++) {
            int i = t + (k << 10);
            int l = lab[i];
            int ll = lab[l];
            if (ll < l) lab[i] = ll;
        }
        __syncthreads();
        if (!any) break;
    }

    int roots = 0;
    #pragma unroll
    for (int k = 0; k < 8; k++) {
        int i = t + (k << 10);
        roots += (lab[i] == i) ? 1 : 0;
    }
    sh[t] = roots;
    __syncthreads();
    for (int s = 512; s > 0; s >>= 1) {
        if (t < s) sh[t] += sh[t + s];
        __syncthreads();
    }
    if (t == 0) {
        float n_comp  = (float)sh[0];
        unsigned half_edges = d_ucount + (d_dcount >> 1);   // (2U+D)//2
        float n_edges = (float)half_edges;
        float betti1  = n_edges - (float)NN + n_comp;
        float n_cyc   = fmaxf(0.0f, betti1);
        float comp_l  = (n_comp - 1.0f) * (n_comp - 1.0f);
        out[0] = comp_l + n_cyc * n_cyc;
    }
    // reset state for the next replay
    d_bcnt[t] = 0u;
    if (t == 0) { d_ucount = 0u; d_dcount = 0u; d_ovfcnt = 0u; }
}

extern "C" void kernel_launch(void* const* d_in, const int* in_sizes, int n_in,
                              void* d_out, int out_size) {
    const float* adj = (const float*)d_in[0];
    float* out = (float*)d_out;

    hc_scan<<<NN / 2, 256>>>(adj);
    hc_finish<<<1, 1024>>>(out);
}

// round 13
// speedup vs baseline: 1.3200x; 1.0245x over previous
#include <cuda_runtime.h>
#include <cuda_bf16.h>

#define NN 8192
#define DCAP 64u              // ELLPACK chunks per node (P(deg>64) ~ 1e-15)
#define OVF_CAP (1u << 16)    // spill safety

// Static scratch. d_deg + counters reset by hc_finish each run.
__device__ unsigned int d_deg[NN];                  // zero at load
__device__ unsigned short d_ell[DCAP * NN];         // 1MB transposed ELLPACK
__device__ unsigned int d_ucount;                   // strictly-upper positives
__device__ unsigned int d_dcount;                   // diagonal positives
__device__ unsigned int d_ovfcnt;
__device__ unsigned int d_ovf[OVF_CAP];

// Scatter one directed entry: chunk-major layout d_ell[c*NN + node] so the
// finish reads are warp-coalesced (lane t reads node t+k*1024 -> 64B/warp).
__device__ __forceinline__ void scatter_dir(int node, int other) {
    unsigned j = atomicAdd(&d_deg[node], 1u);
    if (j < DCAP) {
        d_ell[j * (unsigned)NN + (unsigned)node] = (unsigned short)other;
    } else {
        unsigned o = atomicAdd(&d_ovfcnt, 1u);
        if (o < OVF_CAP) d_ovf[o] = ((unsigned)node << 13) | (unsigned)other;
    }
}

__device__ __forceinline__ void scatter_edge(int u, int v) {
    scatter_dir(u, v);
    scatter_dir(v, u);
}

// Upper-triangle scan, block per row pair (row, NN-1-row): NN+1 elements per
// block -> perfect balance. Hot loop (proven ~4.3 TB/s): 4 batched LDG.128,
// straight-line count, one uniform warp branch via ballot; hits scatter into
// the ELLPACK (8192 distinct L2 atomic counters, hidden under the stream).
// Exactness: adj bitwise symmetric -> full positives = 2U + D; the
// reference's sum(adj>0)//2 = U + D//2 exactly.
__global__ void __launch_bounds__(256) hc_scan(const float* __restrict__ adj) {
    __shared__ unsigned s_cnt;
    const int t = threadIdx.x;
    const int pair = blockIdx.x;
    if (t == 0) s_cnt = 0u;
    __syncthreads();

    #pragma unroll
    for (int half = 0; half < 2; half++) {
        const int row = half ? (NN - 1 - pair) : pair;
        const float4* __restrict__ rowp = (const float4*)(adj + (size_t)row * NN);
        const int start4 = row >> 2;            // quad containing the diagonal

        if (t == 0) {
            // diagonal quad: cols may be <, ==, or > row
            float4 v = rowp[start4];
            int col0 = start4 << 2;
            float e[4] = {v.x, v.y, v.z, v.w};
            unsigned dd = 0, uu = 0;
            #pragma unroll
            for (int j = 0; j < 4; j++) {
                int col = col0 + j;
                if (e[j] > 0.0f) {
                    if (col == row) dd++;
                    else if (col > row) { uu++; scatter_edge(row, col); }
                }
            }
            if (dd) atomicAdd(&d_dcount, dd);
            if (uu) atomicAdd(&s_cnt, uu);
        }

        const int lim = NN / 4;
        for (int ib = start4 + 1; ib < lim; ib += 1024) {
            const float4 NEG = make_float4(-1.f, -1.f, -1.f, -1.f);
            const int i0 = ib + t;
            float4 v0 = NEG, v1 = NEG, v2 = NEG, v3 = NEG;
            if (i0       < lim) v0 = rowp[i0];
            if (i0 + 256 < lim) v1 = rowp[i0 + 256];
            if (i0 + 512 < lim) v2 = rowp[i0 + 512];
            if (i0 + 768 < lim) v3 = rowp[i0 + 768];

            unsigned k = (unsigned)(v0.x > 0.f) + (unsigned)(v0.y > 0.f)
                       + (unsigned)(v0.z > 0.f) + (unsigned)(v0.w > 0.f)
                       + (unsigned)(v1.x > 0.f) + (unsigned)(v1.y > 0.f)
                       + (unsigned)(v1.z > 0.f) + (unsigned)(v1.w > 0.f)
                       + (unsigned)(v2.x > 0.f) + (unsigned)(v2.y > 0.f)
                       + (unsigned)(v2.z > 0.f) + (unsigned)(v2.w > 0.f)
                       + (unsigned)(v3.x > 0.f) + (unsigned)(v3.y > 0.f)
                       + (unsigned)(v3.z > 0.f) + (unsigned)(v3.w > 0.f);

            if (__ballot_sync(0xFFFFFFFFu, k != 0u)) {
                if (k) {
                    atomicAdd(&s_cnt, k);
                    #pragma unroll
                    for (int q = 0; q < 4; q++) {
                        float4 v = (q == 0) ? v0 : (q == 1) ? v1 : (q == 2) ? v2 : v3;
                        int col0 = (i0 + q * 256) << 2;
                        float e[4] = {v.x, v.y, v.z, v.w};
                        #pragma unroll
                        for (int j = 0; j < 4; j++)
                            if (e[j] > 0.f) scatter_edge(row, col0 + j);
                    }
                }
            }
        }
    }

    __syncthreads();
    if (t == 0 && s_cnt) atomicAdd(&d_ucount, s_cnt);
}

// Single block, 1024 threads: pull min-label CC over the transposed ELLPACK.
// Thread t owns nodes {t, t+1024, ...}: ONLY writer of their labels (plain
// STS, zero atomics, monotone -> races benign). Neighbor stream: chunk c of
// node i at d_ell[c*NN + i] -> warp reads 64B contiguous, u16 loads fully
// independent (4-wide batches), min accumulates in a register. A pass with
// no change (edges seen both directions) => labels constant per component
// => lab[i]==i exactly at each component's min node.
__global__ void __launch_bounds__(1024) hc_finish(float* __restrict__ out) {
    __shared__ int lab[NN];                  // 32KB
    __shared__ int sh[1024];
    const int t = threadIdx.x;

    int deg[8];
    #pragma unroll
    for (int k = 0; k < 8; k++) {
        int i = t + (k << 10);
        lab[i] = i;
        deg[k] = (int)min(d_deg[i], DCAP);
    }
    __syncthreads();

    const unsigned novf = min(d_ovfcnt, OVF_CAP);

    for (int iter = 0; iter < 64; iter++) {
        int changed = 0;

        #pragma unroll
        for (int k = 0; k < 8; k++) {
            const int i = t + (k << 10);
            const unsigned short* __restrict__ col = d_ell + i;
            int m = lab[i];
            const int d = deg[k];
            int c = 0;
            for (; c + 4 <= d; c += 4) {
                // 4 independent LDG (coalesced 64B/warp each) + 4 LDS
                int n0 = col[(c + 0) * NN];
                int n1 = col[(c + 1) * NN];
                int n2 = col[(c + 2) * NN];
                int n3 = col[(c + 3) * NN];
                int v0 = lab[n0], v1 = lab[n1];
                int v2 = lab[n2], v3 = lab[n3];
                m = min(m, min(min(v0, v1), min(v2, v3)));
            }
            for (; c < d; c++)
                m = min(m, lab[col[c * NN]]);
            if (m < lab[i]) { lab[i] = m; changed = 1; }   // owner-only STS
        }

        // overflow spill (expected empty; atomics OK here)
        for (unsigned idx = t; idx < novf; idx += 1024) {
            unsigned e = d_ovf[idx];
            int u = (int)(e >> 13), v = (int)(e & 8191u);
            int lu = lab[u], lv = lab[v];
            if (lu != lv) {
                changed = 1;
                if (lu < lv) atomicMin(&lab[v], lu);
                else         atomicMin(&lab[u], lv);
            }
        }

        int any = __syncthreads_or(changed);

        // pointer jump x2 (owner-only, monotone)
        #pragma unroll
        for (int r = 0; r < 2; r++) {
            #pragma unroll
            for (int k = 0; k < 8; k++) {
                int i = t + (k << 10);
                int l = lab[i];
                int ll = lab[l];
                if (ll < l) lab[i] = ll;
            }
            __syncthreads();
        }
        if (!any) break;
    }

    int roots = 0;
    #pragma unroll
    for (int k = 0; k < 8; k++) {
        int i = t + (k << 10);
        roots += (lab[i] == i) ? 1 : 0;
    }
    sh[t] = roots;
    __syncthreads();
    for (int s = 512; s > 0; s >>= 1) {
        if (t < s) sh[t] += sh[t + s];
        __syncthreads();
    }
    if (t == 0) {
        float n_comp  = (float)sh[0];
        unsigned half_edges = d_ucount + (d_dcount >> 1);   // (2U+D)//2
        float n_edges = (float)half_edges;
        float betti1  = n_edges - (float)NN + n_comp;
        float n_cyc   = fmaxf(0.0f, betti1);
        float comp_l  = (n_comp - 1.0f) * (n_comp - 1.0f);
        out[0] = comp_l + n_cyc * n_cyc;
    }
    // reset state for the next replay
    #pragma unroll
    for (int k = 0; k < 8; k++)
        d_deg[t + (k << 10)] = 0u;
    if (t == 0) { d_ucount = 0u; d_dcount = 0u; d_ovfcnt = 0u; }
}

extern "C" void kernel_launch(void* const* d_in, const int* in_sizes, int n_in,
                              void* d_out, int out_size) {
    const float* adj = (const float*)d_in[0];
    float* out = (float*)d_out;

    hc_scan<<<NN / 2, 256>>>(adj);
    hc_finish<<<1, 1024>>>(out);
}